// round 11
// baseline (speedup 1.0000x reference)
#include <cuda_runtime.h>
#include <cstdint>
#include <cmath>

#define TOKENS   16384
#define DMODEL   4096
#define NEXP     64
#define TOPK     8

#define TILE_T   128
#define KCH      32
#define NSTAGE   4
#define NITER    (DMODEL / KCH)

#define XS_STRIDE 36
#define WS_STRIDE 36
#define STAGE_FLOATS (TILE_T * XS_STRIDE + NEXP * WS_STRIDE)
#define SMEM_BYTES (NSTAGE * STAGE_FLOATS * 4)

// exp flush/clamp boundary ~ ln(2^-126)
#define T_F (-87.33654022f)
#define FLT_MIN_NORM 1.1754943508222875e-38

#define K2_BLOCKS 64

__device__ int g_count;
__device__ int g_list[TOKENS];

__device__ __forceinline__ void cp_async16(void* smem_dst, const void* gmem_src) {
    uint32_t dst = (uint32_t)__cvta_generic_to_shared(smem_dst);
    asm volatile("cp.async.cg.shared.global [%0], [%1], 16;\n" :: "r"(dst), "l"(gmem_src));
}
__device__ __forceinline__ void cp_async_commit() {
    asm volatile("cp.async.commit_group;\n");
}
template <int N>
__device__ __forceinline__ void cp_async_wait() {
    asm volatile("cp.async.wait_group %0;\n" :: "n"(N));
}
__device__ __forceinline__ void fma2(unsigned long long& d,
                                     unsigned long long a,
                                     unsigned long long b) {
    asm("fma.rn.f32x2 %0, %1, %2, %0;" : "+l"(d) : "l"(a), "l"(b));
}

// epilogue with FLUSH-ON-DIVISION tie semantics:
// q = exp(max(d, T_F)) / sum; if q < 2^-126 (subnormal quotient) -> tie group
// (key 0, filled ascending index); else rank by fp32 bits of q.
// For sum ~= 1 this reduces exactly to the R6 rule (boundary at T_F).
__device__ __forceinline__ void epilogue_topk(const float* row, float* ow, float* oi)
{
    float m = row[0];
#pragma unroll 8
    for (int e = 1; e < NEXP; e++) m = fmaxf(m, row[e]);

    float sum = 0.0f;
    for (int e = 0; e < NEXP; e++) {
        float d = row[e] - m;
        if (d >= T_F) sum += __expf(d);
    }
    const double sumd = (double)sum;

    int keys[TOPK];
    int idxs[TOPK];
#pragma unroll
    for (int j = 0; j < TOPK; j++) { keys[j] = -1; idxs[j] = 0; }

    for (int e = 0; e < NEXP; e++) {
        double dd = (double)(row[e] - m);
        if (dd < (double)T_F) dd = (double)T_F;     // exp clamp/flush equivalence
        double q = exp(dd) / sumd;
        int key = (q < FLT_MIN_NORM) ? 0            // subnormal quotient flushed -> tie
                                     : __float_as_int((float)q);
        if (key > keys[TOPK - 1]) {
            keys[TOPK - 1] = key;
            idxs[TOPK - 1] = e;
#pragma unroll
            for (int q2 = TOPK - 1; q2 > 0; q2--) {
                if (keys[q2] > keys[q2 - 1]) {
                    int tk = keys[q2]; keys[q2] = keys[q2 - 1]; keys[q2 - 1] = tk;
                    int ti = idxs[q2]; idxs[q2] = idxs[q2 - 1]; idxs[q2 - 1] = ti;
                }
            }
        }
    }
#pragma unroll
    for (int j = 0; j < TOPK; j++) {
        ow[j] = __int_as_float(keys[j] == 0 ? 0 : keys[j]);
        oi[j] = (float)idxs[j];
    }
}

__global__ void reset_kernel() { if (threadIdx.x == 0) g_count = 0; }

// ---------------- kernel 1: fast fp32 GEMM + epilogue + ambiguity flagging ----------------
__global__ void __launch_bounds__(256, 1)
router_kernel(const float* __restrict__ x, const float* __restrict__ w,
              float* __restrict__ out_w, float* __restrict__ out_i)
{
    extern __shared__ float smem[];
    const int tid = threadIdx.x;
    const int tx  = tid & 15;
    const int ty  = tid >> 4;
    const int t_block = blockIdx.x * TILE_T;

    unsigned long long acc2[8][4];
#pragma unroll
    for (int i = 0; i < 8; i++)
#pragma unroll
        for (int j = 0; j < 4; j++) acc2[i][j] = 0ULL;

    auto issue_stage = [&](int stage, int it) {
        float* xs = smem + stage * STAGE_FLOATS;
        float* ws = xs + TILE_T * XS_STRIDE;
        const int kc = it * KCH;
#pragma unroll
        for (int q = 0; q < 4; q++) {
            int seg = tid + 256 * q;
            int row = seg >> 3;
            int c   = (seg & 7) * 4;
            cp_async16(&xs[row * XS_STRIDE + c],
                       &x[(size_t)(t_block + row) * DMODEL + kc + c]);
        }
#pragma unroll
        for (int q = 0; q < 2; q++) {
            int seg = tid + 256 * q;
            int row = seg >> 3;
            int c   = (seg & 7) * 4;
            cp_async16(&ws[row * WS_STRIDE + c],
                       &w[(size_t)row * DMODEL + kc + c]);
        }
        cp_async_commit();
    };

    for (int s = 0; s < NSTAGE - 1; s++) issue_stage(s, s);

    for (int it = 0; it < NITER; it++) {
        cp_async_wait<NSTAGE - 2>();
        __syncthreads();

        const float* xs = smem + (it & (NSTAGE - 1)) * STAGE_FLOATS;
        const float* ws = xs + TILE_T * XS_STRIDE;

#pragma unroll
        for (int k4 = 0; k4 < KCH / 4; k4++) {
            ulonglong2 wf2[4];
#pragma unroll
            for (int j = 0; j < 4; j++)
                wf2[j] = *(const ulonglong2*)&ws[(tx + 16 * j) * WS_STRIDE + k4 * 4];
#pragma unroll
            for (int i = 0; i < 8; i++) {
                ulonglong2 xf2 = *(const ulonglong2*)&xs[(ty + 16 * i) * XS_STRIDE + k4 * 4];
#pragma unroll
                for (int j = 0; j < 4; j++) {
                    fma2(acc2[i][j], xf2.x, wf2[j].x);
                    fma2(acc2[i][j], xf2.y, wf2[j].y);
                }
            }
        }

        int nxt = it + NSTAGE - 1;
        if (nxt < NITER) issue_stage(nxt & (NSTAGE - 1), nxt);
        else             cp_async_commit();
    }

    __syncthreads();
    float* lsm = smem;   // [128][65]
#pragma unroll
    for (int i = 0; i < 8; i++)
#pragma unroll
        for (int j = 0; j < 4; j++) {
            float2 p = *(float2*)&acc2[i][j];
            lsm[(ty + 16 * i) * 65 + (tx + 16 * j)] = p.x + p.y;
        }
    __syncthreads();

    if (tid < TILE_T) {
        const float* row = lsm + tid * 65;

        float m = row[0];
#pragma unroll 8
        for (int e = 1; e < NEXP; e++) m = fmaxf(m, row[e]);

        float sum = 0.0f;
        for (int e = 0; e < NEXP; e++) {
            float d = row[e] - m;
            if (d >= T_F) sum += __expf(d);
        }
        // effective tie boundary after division flush: T_F + ln(sum)
        float bnd = T_F + __logf(sum);

        // ambiguity detection: near either boundary, or near-degenerate top-9 gap
        float dt[9];
#pragma unroll
        for (int q = 0; q < 9; q++) dt[q] = -3.0e38f;
        bool flag = false;
        for (int e = 0; e < NEXP; e++) {
            float d = row[e] - m;
            if (fabsf(d - T_F) < 0.05f || fabsf(d - bnd) < 0.05f) flag = true;
            if (d > dt[8]) {
                dt[8] = d;
#pragma unroll
                for (int q = 8; q > 0; q--)
                    if (dt[q] > dt[q - 1]) { float t = dt[q]; dt[q] = dt[q - 1]; dt[q - 1] = t; }
            }
        }
#pragma unroll
        for (int q = 0; q < 8; q++)
            if (dt[q] - dt[q + 1] < 0.003f && dt[q + 1] > T_F - 0.05f) flag = true;

        int gtok = t_block + tid;
        if (flag) {
            int slot = atomicAdd(&g_count, 1);
            if (slot < TOKENS) g_list[slot] = gtok;
        }

        epilogue_topk(row, out_w + (size_t)gtok * TOPK, out_i + (size_t)gtok * TOPK);
    }
}

// ---------------- kernel 2: fp64 re-resolution of flagged tokens ----------------
// fp64 logits (8 independent partials -> latency-hidden) + same epilogue.
// Proven decision-neutral (R7); guards noise-straddle at boundaries.
__global__ void __launch_bounds__(256, 1)
router_fixup(const float* __restrict__ x, const float* __restrict__ w,
             float* __restrict__ out_w, float* __restrict__ out_i)
{
    __shared__ float lg[4][NEXP];

    const int tid  = threadIdx.x;
    const int slot = tid >> 6;     // 4 tokens per block
    const int e    = tid & 63;     // expert per thread

    int total = g_count;
    if (total > TOKENS) total = TOKENS;

    for (int base = blockIdx.x * 4; base < total; base += K2_BLOCKS * 4) {
        int li  = base + slot;
        int tok = (li < total) ? g_list[li] : -1;

        if (tok >= 0) {
            const float* xr = x + (size_t)tok * DMODEL;
            const float* wr = w + (size_t)e   * DMODEL;

            double p0 = 0, p1 = 0, p2 = 0, p3 = 0, p4 = 0, p5 = 0, p6 = 0, p7 = 0;
            for (int k = 0; k < DMODEL; k += 8) {
                p0 = fma((double)xr[k+0], (double)wr[k+0], p0);
                p1 = fma((double)xr[k+1], (double)wr[k+1], p1);
                p2 = fma((double)xr[k+2], (double)wr[k+2], p2);
                p3 = fma((double)xr[k+3], (double)wr[k+3], p3);
                p4 = fma((double)xr[k+4], (double)wr[k+4], p4);
                p5 = fma((double)xr[k+5], (double)wr[k+5], p5);
                p6 = fma((double)xr[k+6], (double)wr[k+6], p6);
                p7 = fma((double)xr[k+7], (double)wr[k+7], p7);
            }
            lg[slot][e] = (float)(((p0 + p1) + (p2 + p3)) + ((p4 + p5) + (p6 + p7)));
        }
        __syncthreads();

        if (tok >= 0 && e == 0)
            epilogue_topk(lg[slot], out_w + (size_t)tok * TOPK, out_i + (size_t)tok * TOPK);
        __syncthreads();
    }
}

extern "C" void kernel_launch(void* const* d_in, const int* in_sizes, int n_in,
                              void* d_out, int out_size)
{
    const float* x = (const float*)d_in[0];
    const float* w = (const float*)d_in[1];

    float* out_w = (float*)d_out;
    float* out_i = (float*)d_out + (size_t)TOKENS * TOPK;

    cudaFuncSetAttribute(router_kernel,
                         cudaFuncAttributeMaxDynamicSharedMemorySize, SMEM_BYTES);

    reset_kernel<<<1, 32>>>();
    router_kernel<<<TOKENS / TILE_T, 256, SMEM_BYTES>>>(x, w, out_w, out_i);
    router_fixup<<<K2_BLOCKS, 256>>>(x, w, out_w, out_i);
}

// round 12
// speedup vs baseline: 2.2924x; 2.2924x over previous
#include <cuda_runtime.h>
#include <cstdint>
#include <cmath>

#define TOKENS   16384
#define DMODEL   4096
#define NEXP     64
#define TOPK     8

#define TILE_T   128
#define KCH      32
#define NSTAGE   4
#define NITER    (DMODEL / KCH)

#define XS_STRIDE 36
#define WS_STRIDE 36
#define STAGE_FLOATS (TILE_T * XS_STRIDE + NEXP * WS_STRIDE)
#define SMEM_BYTES (NSTAGE * STAGE_FLOATS * 4)

// exp flush/clamp boundary ~ ln(2^-126)
#define T_F (-87.33654022f)
#define FLT_MIN_NORM 1.1754943508222875e-38

#define K2_BLOCKS 256

__device__ int g_count;
__device__ int g_list[TOKENS];

__device__ __forceinline__ void cp_async16(void* smem_dst, const void* gmem_src) {
    uint32_t dst = (uint32_t)__cvta_generic_to_shared(smem_dst);
    asm volatile("cp.async.cg.shared.global [%0], [%1], 16;\n" :: "r"(dst), "l"(gmem_src));
}
__device__ __forceinline__ void cp_async_commit() {
    asm volatile("cp.async.commit_group;\n");
}
template <int N>
__device__ __forceinline__ void cp_async_wait() {
    asm volatile("cp.async.wait_group %0;\n" :: "n"(N));
}
__device__ __forceinline__ void fma2(unsigned long long& d,
                                     unsigned long long a,
                                     unsigned long long b) {
    asm("fma.rn.f32x2 %0, %1, %2, %0;" : "+l"(d) : "l"(a), "l"(b));
}

// ---- PASSING epilogue (R11) — DO NOT CHANGE SEMANTICS ----
// flush-on-division ties: q = exp(max(d,T_F))/sum; q < 2^-126 -> tie group
// (key 0, ascending index); else rank by fp32 bits of q.
__device__ __forceinline__ void epilogue_topk(const float* row, float* ow, float* oi)
{
    float m = row[0];
#pragma unroll 8
    for (int e = 1; e < NEXP; e++) m = fmaxf(m, row[e]);

    float sum = 0.0f;
    for (int e = 0; e < NEXP; e++) {
        float d = row[e] - m;
        if (d >= T_F) sum += __expf(d);
    }
    const double sumd = (double)sum;

    int keys[TOPK];
    int idxs[TOPK];
#pragma unroll
    for (int j = 0; j < TOPK; j++) { keys[j] = -1; idxs[j] = 0; }

    // clamped-expert key is identical for all d < T_F: compute once
    double qc = exp((double)T_F) / sumd;
    const int key_clamp = (qc < FLT_MIN_NORM) ? 0 : __float_as_int((float)qc);

    for (int e = 0; e < NEXP; e++) {
        float d = row[e] - m;
        int key;
        if (d < T_F) {
            key = key_clamp;
        } else {
            double q = exp((double)d) / sumd;
            key = (q < FLT_MIN_NORM) ? 0 : __float_as_int((float)q);
        }
        if (key > keys[TOPK - 1]) {
            keys[TOPK - 1] = key;
            idxs[TOPK - 1] = e;
#pragma unroll
            for (int q2 = TOPK - 1; q2 > 0; q2--) {
                if (keys[q2] > keys[q2 - 1]) {
                    int tk = keys[q2]; keys[q2] = keys[q2 - 1]; keys[q2 - 1] = tk;
                    int ti = idxs[q2]; idxs[q2] = idxs[q2 - 1]; idxs[q2 - 1] = ti;
                }
            }
        }
    }
#pragma unroll
    for (int j = 0; j < TOPK; j++) {
        ow[j] = __int_as_float(keys[j] < 0 ? 0 : keys[j]);
        oi[j] = (float)idxs[j];
    }
}

__global__ void reset_kernel() { if (threadIdx.x == 0) g_count = 0; }

// ---------------- kernel 1: fast fp32 GEMM + epilogue + ambiguity flagging ----------------
__global__ void __launch_bounds__(256, 1)
router_kernel(const float* __restrict__ x, const float* __restrict__ w,
              float* __restrict__ out_w, float* __restrict__ out_i)
{
    extern __shared__ float smem[];
    const int tid = threadIdx.x;
    const int tx  = tid & 15;
    const int ty  = tid >> 4;
    const int t_block = blockIdx.x * TILE_T;

    unsigned long long acc2[8][4];
#pragma unroll
    for (int i = 0; i < 8; i++)
#pragma unroll
        for (int j = 0; j < 4; j++) acc2[i][j] = 0ULL;

    auto issue_stage = [&](int stage, int it) {
        float* xs = smem + stage * STAGE_FLOATS;
        float* ws = xs + TILE_T * XS_STRIDE;
        const int kc = it * KCH;
#pragma unroll
        for (int q = 0; q < 4; q++) {
            int seg = tid + 256 * q;
            int row = seg >> 3;
            int c   = (seg & 7) * 4;
            cp_async16(&xs[row * XS_STRIDE + c],
                       &x[(size_t)(t_block + row) * DMODEL + kc + c]);
        }
#pragma unroll
        for (int q = 0; q < 2; q++) {
            int seg = tid + 256 * q;
            int row = seg >> 3;
            int c   = (seg & 7) * 4;
            cp_async16(&ws[row * WS_STRIDE + c],
                       &w[(size_t)row * DMODEL + kc + c]);
        }
        cp_async_commit();
    };

    for (int s = 0; s < NSTAGE - 1; s++) issue_stage(s, s);

    for (int it = 0; it < NITER; it++) {
        cp_async_wait<NSTAGE - 2>();
        __syncthreads();

        const float* xs = smem + (it & (NSTAGE - 1)) * STAGE_FLOATS;
        const float* ws = xs + TILE_T * XS_STRIDE;

#pragma unroll
        for (int k4 = 0; k4 < KCH / 4; k4++) {
            ulonglong2 wf2[4];
#pragma unroll
            for (int j = 0; j < 4; j++)
                wf2[j] = *(const ulonglong2*)&ws[(tx + 16 * j) * WS_STRIDE + k4 * 4];
#pragma unroll
            for (int i = 0; i < 8; i++) {
                ulonglong2 xf2 = *(const ulonglong2*)&xs[(ty + 16 * i) * XS_STRIDE + k4 * 4];
#pragma unroll
                for (int j = 0; j < 4; j++) {
                    fma2(acc2[i][j], xf2.x, wf2[j].x);
                    fma2(acc2[i][j], xf2.y, wf2[j].y);
                }
            }
        }

        int nxt = it + NSTAGE - 1;
        if (nxt < NITER) issue_stage(nxt & (NSTAGE - 1), nxt);
        else             cp_async_commit();
    }

    __syncthreads();
    float* lsm = smem;   // [128][65]
#pragma unroll
    for (int i = 0; i < 8; i++)
#pragma unroll
        for (int j = 0; j < 4; j++) {
            float2 p = *(float2*)&acc2[i][j];
            lsm[(ty + 16 * i) * 65 + (tx + 16 * j)] = p.x + p.y;
        }
    __syncthreads();

    if (tid < TILE_T) {
        const float* row = lsm + tid * 65;

        float m = row[0];
#pragma unroll 8
        for (int e = 1; e < NEXP; e++) m = fmaxf(m, row[e]);

        float sum = 0.0f;
        for (int e = 0; e < NEXP; e++) {
            float d = row[e] - m;
            if (d >= T_F) sum += __expf(d);
        }
        // effective tie boundary after division flush: T_F + ln(sum)
        float bnd = T_F + __logf(sum);

        // ambiguity detection (identical to passing R11 config)
        float dt[9];
#pragma unroll
        for (int q = 0; q < 9; q++) dt[q] = -3.0e38f;
        bool flag = false;
        for (int e = 0; e < NEXP; e++) {
            float d = row[e] - m;
            if (fabsf(d - T_F) < 0.05f || fabsf(d - bnd) < 0.05f) flag = true;
            if (d > dt[8]) {
                dt[8] = d;
#pragma unroll
                for (int q = 8; q > 0; q--)
                    if (dt[q] > dt[q - 1]) { float t = dt[q]; dt[q] = dt[q - 1]; dt[q - 1] = t; }
            }
        }
#pragma unroll
        for (int q = 0; q < 8; q++)
            if (dt[q] - dt[q + 1] < 0.003f && dt[q + 1] > T_F - 0.05f) flag = true;

        int gtok = t_block + tid;
        if (flag) {
            int slot = atomicAdd(&g_count, 1);
            if (slot < TOKENS) g_list[slot] = gtok;
        }

        epilogue_topk(row, out_w + (size_t)gtok * TOPK, out_i + (size_t)gtok * TOPK);
    }
}

// ---------------- kernel 2: COALESCED fp64 re-resolution of flagged tokens ----------------
// One token per block pass; warp wid owns experts 8*wid..8*wid+7; lanes stride
// k by 32 -> every x/w load is a 128B coalesced line. 8 interleaved fp64
// accumulators per lane hide DFMA latency; double shuffle-reduce per expert.
__global__ void __launch_bounds__(256, 1)
router_fixup(const float* __restrict__ x, const float* __restrict__ w,
             float* __restrict__ out_w, float* __restrict__ out_i)
{
    __shared__ float lg[NEXP];

    const int tid  = threadIdx.x;
    const int wid  = tid >> 5;
    const int lane = tid & 31;

    int total = g_count;
    if (total > TOKENS) total = TOKENS;

    for (int li = blockIdx.x; li < total; li += K2_BLOCKS) {
        int tok = g_list[li];
        const float* xr = x + (size_t)tok * DMODEL;
        const float* w0 = w + (size_t)(wid * 8) * DMODEL;

        double acc[8];
#pragma unroll
        for (int e8 = 0; e8 < 8; e8++) acc[e8] = 0.0;

        for (int k = lane; k < DMODEL; k += 32) {
            double xv = (double)xr[k];
#pragma unroll
            for (int e8 = 0; e8 < 8; e8++)
                acc[e8] = fma(xv, (double)w0[e8 * DMODEL + k], acc[e8]);
        }

#pragma unroll
        for (int e8 = 0; e8 < 8; e8++) {
            double s = acc[e8];
#pragma unroll
            for (int o = 16; o; o >>= 1) s += __shfl_down_sync(0xFFFFFFFFu, s, o);
            if (lane == 0) lg[wid * 8 + e8] = (float)s;
        }
        __syncthreads();

        if (tid == 0)
            epilogue_topk(lg, out_w + (size_t)tok * TOPK, out_i + (size_t)tok * TOPK);
        __syncthreads();
    }
}

extern "C" void kernel_launch(void* const* d_in, const int* in_sizes, int n_in,
                              void* d_out, int out_size)
{
    const float* x = (const float*)d_in[0];
    const float* w = (const float*)d_in[1];

    float* out_w = (float*)d_out;
    float* out_i = (float*)d_out + (size_t)TOKENS * TOPK;

    cudaFuncSetAttribute(router_kernel,
                         cudaFuncAttributeMaxDynamicSharedMemorySize, SMEM_BYTES);

    reset_kernel<<<1, 32>>>();
    router_kernel<<<TOKENS / TILE_T, 256, SMEM_BYTES>>>(x, w, out_w, out_i);
    router_fixup<<<K2_BLOCKS, 256>>>(x, w, out_w, out_i);
}